// round 6
// baseline (speedup 1.0000x reference)
#include <cuda_runtime.h>
#include <stdint.h>
#include <math.h>

#define MAXN 50000
#define MAXE 800000
#define NF 256

// ---------------- scratch (device globals; no allocation allowed) ----------
__device__ float g_h[(size_t)MAXN * NF];     // GEMM output (pre-aggregation features)
__device__ float g_buf[(size_t)MAXN * NF];   // layer output (post LN+ELU) = next layer input
// per-layer alpha buffers: [layer][asrc|adst][MAXN*4]
__device__ float g_alpha[(size_t)6 * MAXN * 4];
__device__ int   g_cnt[MAXN];                // zero-initialized; scan re-zeroes for next call
__device__ int   g_rowptr[MAXN + 1];
__device__ int   g_cursor[MAXN];
__device__ int   g_colsrc[MAXE];

// ---------------- CSR build ------------------------------------------------
// hist also zeroes the alpha accumulation buffers (needed before each gemm).
__global__ void hist_kernel(const int* __restrict__ dst, int* __restrict__ cnt,
                            float* __restrict__ alpha, int e) {
    int t = blockIdx.x * blockDim.x + threadIdx.x;
    if (t < e) atomicAdd(&cnt[dst[t]], 1);
    const int total = 6 * MAXN * 4;
    for (int i = t; i < total; i += gridDim.x * blockDim.x) alpha[i] = 0.f;
}

__global__ void scan_kernel(int* __restrict__ cnt, int* __restrict__ rowptr,
                            int* __restrict__ cursor, int n) {
    __shared__ int sh[1024];
    int tid = threadIdx.x;
    int chunk = (n + 1023) >> 10;
    int base = tid * chunk;
    int s = 0;
    for (int j = 0; j < chunk; j++) {
        int idx = base + j;
        if (idx < n) s += cnt[idx];
    }
    sh[tid] = s;
    __syncthreads();
    for (int off = 1; off < 1024; off <<= 1) {
        int v = (tid >= off) ? sh[tid - off] : 0;
        __syncthreads();
        sh[tid] += v;
        __syncthreads();
    }
    int run = sh[tid] - s;  // exclusive prefix
    for (int j = 0; j < chunk; j++) {
        int idx = base + j;
        if (idx < n) {
            rowptr[idx] = run;
            cursor[idx] = run;
            run += cnt[idx];
            cnt[idx] = 0;   // re-zero for the next kernel_launch call (graph replay)
        }
    }
    if (tid == 1023) rowptr[n] = run;
}

__global__ void scatter_kernel(const int* __restrict__ src, const int* __restrict__ dst,
                               int* __restrict__ cursor, int* __restrict__ colsrc, int e) {
    int t = blockIdx.x * blockDim.x + threadIdx.x;
    if (t < e) {
        int d = dst[t];
        int p = atomicAdd(&cursor[d], 1);
        colsrc[p] = src[t];
    }
}

// ---------------- tf32 helpers ----------------------------------------------
__device__ __forceinline__ float tf32_rna(float x) {
    uint32_t u;
    asm("cvt.rna.tf32.f32 %0, %1;" : "=r"(u) : "f"(x));
    return __uint_as_float(u);
}

__device__ __forceinline__ void mma_tf32(float c[4],
                                         uint32_t a0, uint32_t a1, uint32_t a2, uint32_t a3,
                                         uint32_t b0, uint32_t b1) {
    asm volatile(
        "mma.sync.aligned.m16n8k8.row.col.f32.tf32.tf32.f32 "
        "{%0,%1,%2,%3}, {%4,%5,%6,%7}, {%8,%9}, {%0,%1,%2,%3};"
        : "+f"(c[0]), "+f"(c[1]), "+f"(c[2]), "+f"(c[3])
        : "r"(a0), "r"(a1), "r"(a2), "r"(a3), "r"(b0), "r"(b1));
}

// ---------------- tensor-core GEMM + fused alpha projection -----------------
template <int H>
__global__ void __launch_bounds__(256, 2) gemm_tc(
    const float* __restrict__ A, const float* __restrict__ B,
    float* __restrict__ C, int M, int K,
    const float* __restrict__ a_s, const float* __restrict__ a_d,
    float* __restrict__ asrc, float* __restrict__ adst)
{
    __shared__ float4 As_hi4[128 * 5];   // 128 rows x 20 floats
    __shared__ float4 As_lo4[128 * 5];
    __shared__ float4 Bs_hi4[16 * 34];   // 16 k-rows x 136 floats
    __shared__ float4 Bs_lo4[16 * 34];
    const float* As_hi = (const float*)As_hi4;
    const float* As_lo = (const float*)As_lo4;
    const float* Bs_hi = (const float*)Bs_hi4;
    const float* Bs_lo = (const float*)Bs_lo4;

    const int tid  = threadIdx.x;
    const int lane = tid & 31;
    const int w    = tid >> 5;
    const int g    = lane >> 2;
    const int t    = lane & 3;
    const int wm   = w >> 2;
    const int wn   = w & 3;

    const int row0 = blockIdx.y * 128;
    const int col0 = blockIdx.x * 128;

    const int ar0 = tid >> 2;
    const int ar1 = 64 + (tid >> 2);
    const int ac4 = tid & 3;
    const int bk0 = tid >> 5;
    const int bk1 = 8 + (tid >> 5);
    const int bc4 = tid & 31;

    const bool ok0 = (row0 + ar0) < M;
    const bool ok1 = (row0 + ar1) < M;

    float acc[4][4][4];
#pragma unroll
    for (int mt = 0; mt < 4; mt++)
#pragma unroll
        for (int nt = 0; nt < 4; nt++)
#pragma unroll
            for (int i = 0; i < 4; i++) acc[mt][nt][i] = 0.f;

    const float4 z4 = make_float4(0.f, 0.f, 0.f, 0.f);
    float4 pa0, pa1, pb0, pb1;

    pa0 = ok0 ? *(const float4*)(A + (size_t)(row0 + ar0) * K + ac4 * 4) : z4;
    pa1 = ok1 ? *(const float4*)(A + (size_t)(row0 + ar1) * K + ac4 * 4) : z4;
    pb0 = *(const float4*)(B + (size_t)bk0 * NF + col0 + bc4 * 4);
    pb1 = *(const float4*)(B + (size_t)bk1 * NF + col0 + bc4 * 4);

    for (int kt = 0; kt < K; kt += 16) {
        {
            float4 h, l;
            h.x = tf32_rna(pa0.x); l.x = tf32_rna(pa0.x - h.x);
            h.y = tf32_rna(pa0.y); l.y = tf32_rna(pa0.y - h.y);
            h.z = tf32_rna(pa0.z); l.z = tf32_rna(pa0.z - h.z);
            h.w = tf32_rna(pa0.w); l.w = tf32_rna(pa0.w - h.w);
            As_hi4[ar0 * 5 + ac4] = h; As_lo4[ar0 * 5 + ac4] = l;
            h.x = tf32_rna(pa1.x); l.x = tf32_rna(pa1.x - h.x);
            h.y = tf32_rna(pa1.y); l.y = tf32_rna(pa1.y - h.y);
            h.z = tf32_rna(pa1.z); l.z = tf32_rna(pa1.z - h.z);
            h.w = tf32_rna(pa1.w); l.w = tf32_rna(pa1.w - h.w);
            As_hi4[ar1 * 5 + ac4] = h; As_lo4[ar1 * 5 + ac4] = l;
            h.x = tf32_rna(pb0.x); l.x = tf32_rna(pb0.x - h.x);
            h.y = tf32_rna(pb0.y); l.y = tf32_rna(pb0.y - h.y);
            h.z = tf32_rna(pb0.z); l.z = tf32_rna(pb0.z - h.z);
            h.w = tf32_rna(pb0.w); l.w = tf32_rna(pb0.w - h.w);
            Bs_hi4[bk0 * 34 + bc4] = h; Bs_lo4[bk0 * 34 + bc4] = l;
            h.x = tf32_rna(pb1.x); l.x = tf32_rna(pb1.x - h.x);
            h.y = tf32_rna(pb1.y); l.y = tf32_rna(pb1.y - h.y);
            h.z = tf32_rna(pb1.z); l.z = tf32_rna(pb1.z - h.z);
            h.w = tf32_rna(pb1.w); l.w = tf32_rna(pb1.w - h.w);
            Bs_hi4[bk1 * 34 + bc4] = h; Bs_lo4[bk1 * 34 + bc4] = l;
        }
        __syncthreads();

        int ktn = kt + 16;
        if (ktn < K) {
            pa0 = ok0 ? *(const float4*)(A + (size_t)(row0 + ar0) * K + ktn + ac4 * 4) : z4;
            pa1 = ok1 ? *(const float4*)(A + (size_t)(row0 + ar1) * K + ktn + ac4 * 4) : z4;
            pb0 = *(const float4*)(B + (size_t)(ktn + bk0) * NF + col0 + bc4 * 4);
            pb1 = *(const float4*)(B + (size_t)(ktn + bk1) * NF + col0 + bc4 * 4);
        }

#pragma unroll
        for (int kk = 0; kk < 16; kk += 8) {
            uint32_t bh[4][2], bl[4][2];
            const int cb = wn * 32;
#pragma unroll
            for (int nt = 0; nt < 4; nt++) {
                int col = cb + nt * 8 + g;
                bh[nt][0] = __float_as_uint(Bs_hi[(kk + t) * 136 + col]);
                bh[nt][1] = __float_as_uint(Bs_hi[(kk + t + 4) * 136 + col]);
                bl[nt][0] = __float_as_uint(Bs_lo[(kk + t) * 136 + col]);
                bl[nt][1] = __float_as_uint(Bs_lo[(kk + t + 4) * 136 + col]);
            }
#pragma unroll
            for (int mt = 0; mt < 4; mt++) {
                int rb = wm * 64 + mt * 16 + g;
                uint32_t ah[4], al[4];
                ah[0] = __float_as_uint(As_hi[rb * 20 + kk + t]);
                ah[1] = __float_as_uint(As_hi[(rb + 8) * 20 + kk + t]);
                ah[2] = __float_as_uint(As_hi[rb * 20 + kk + t + 4]);
                ah[3] = __float_as_uint(As_hi[(rb + 8) * 20 + kk + t + 4]);
                al[0] = __float_as_uint(As_lo[rb * 20 + kk + t]);
                al[1] = __float_as_uint(As_lo[(rb + 8) * 20 + kk + t]);
                al[2] = __float_as_uint(As_lo[rb * 20 + kk + t + 4]);
                al[3] = __float_as_uint(As_lo[(rb + 8) * 20 + kk + t + 4]);
#pragma unroll
                for (int nt = 0; nt < 4; nt++) {
                    mma_tf32(acc[mt][nt], ah[0], ah[1], ah[2], ah[3], bh[nt][0], bh[nt][1]);
                    mma_tf32(acc[mt][nt], ah[0], ah[1], ah[2], ah[3], bl[nt][0], bl[nt][1]);
                    mma_tf32(acc[mt][nt], al[0], al[1], al[2], al[3], bh[nt][0], bh[nt][1]);
                }
            }
        }
        __syncthreads();
    }

    // ---- epilogue 1: store C tile ----
#pragma unroll
    for (int mt = 0; mt < 4; mt++) {
        int r0 = row0 + wm * 64 + mt * 16 + g;
        int r1 = r0 + 8;
#pragma unroll
        for (int nt = 0; nt < 4; nt++) {
            int col = col0 + wn * 32 + nt * 8 + 2 * t;
            if (r0 < M)
                *(float2*)(C + (size_t)r0 * NF + col) = make_float2(acc[mt][nt][0], acc[mt][nt][1]);
            if (r1 < M)
                *(float2*)(C + (size_t)r1 * NF + col) = make_float2(acc[mt][nt][2], acc[mt][nt][3]);
        }
    }

    // ---- epilogue 2: fused alpha projection ----
    {
        float asv[4][2], adv[4][2];
#pragma unroll
        for (int nt = 0; nt < 4; nt++)
#pragma unroll
            for (int i = 0; i < 2; i++) {
                int gcol = col0 + wn * 32 + nt * 8 + 2 * t + i;
                asv[nt][i] = a_s[gcol];
                adv[nt][i] = a_d[gcol];
            }
        const int hd = (H == 4) ? ((col0 + wn * 32) >> 6) : 0;
#pragma unroll
        for (int mt = 0; mt < 4; mt++) {
            float sa0 = 0.f, sd0 = 0.f, sa1 = 0.f, sd1 = 0.f;
#pragma unroll
            for (int nt = 0; nt < 4; nt++)
#pragma unroll
                for (int i = 0; i < 2; i++) {
                    sa0 += acc[mt][nt][i]     * asv[nt][i];
                    sd0 += acc[mt][nt][i]     * adv[nt][i];
                    sa1 += acc[mt][nt][2 + i] * asv[nt][i];
                    sd1 += acc[mt][nt][2 + i] * adv[nt][i];
                }
#pragma unroll
            for (int o = 1; o <= 2; o <<= 1) {
                sa0 += __shfl_xor_sync(0xffffffffu, sa0, o);
                sd0 += __shfl_xor_sync(0xffffffffu, sd0, o);
                sa1 += __shfl_xor_sync(0xffffffffu, sa1, o);
                sd1 += __shfl_xor_sync(0xffffffffu, sd1, o);
            }
            if (t == 0) {
                int r0 = row0 + wm * 64 + mt * 16 + g;
                int r1 = r0 + 8;
                if (r0 < M) {
                    atomicAdd(&asrc[r0 * H + hd], sa0);
                    atomicAdd(&adst[r0 * H + hd], sd0);
                }
                if (r1 < M) {
                    atomicAdd(&asrc[r1 * H + hd], sa1);
                    atomicAdd(&adst[r1 * H + hd], sd1);
                }
            }
        }
    }
}

// ---------------- block-sum helper (256 threads) -----------------------------
__device__ __forceinline__ float block_sum256(float v, float* red) {
#pragma unroll
    for (int o = 16; o > 0; o >>= 1) v += __shfl_xor_sync(0xffffffffu, v, o);
    int wid = threadIdx.x >> 5;
    if ((threadIdx.x & 31) == 0) red[wid] = v;
    __syncthreads();
    float s = 0.f;
#pragma unroll
    for (int w = 0; w < 8; w++) s += red[w];
    __syncthreads();
    return s;
}

// ---------------- fused aggregation + softmax + bias + LN + ELU ------------
// One block per destination node. 4 edge-groups x 64 channel-threads;
// each thread handles 4 channels via float4 (LDG.128), 4 edges in flight.
template <int H>
__global__ void __launch_bounds__(256) agg_kernel(
    const float4* __restrict__ hfeat4,
    const float* __restrict__ asrc, const float* __restrict__ adst,
    const int* __restrict__ rowptr, const int* __restrict__ colsrc,
    const float4* __restrict__ bias4, const float4* __restrict__ lnw4,
    const float4* __restrict__ lnb4, float4* __restrict__ out4)
{
    int i   = blockIdx.x;
    int tid = threadIdx.x;
    int gid = tid >> 6;          // edge group 0..3
    int ch4 = tid & 63;          // float4 channel index 0..63
    int head = (H == 4) ? (ch4 >> 4) : 0;

    __shared__ int    sh_src[32];
    __shared__ float  sh_ex[32][H];
    __shared__ float  sh_ad[H];
    __shared__ float4 racc[4][64];
    __shared__ float  rden[4][64];
    __shared__ float  red[8];

    if (tid < H) sh_ad[tid] = adst[i * H + tid];

    float4 acc = make_float4(0.f, 0.f, 0.f, 0.f);
    float  den = 0.f;

    // self-loop (group 0 only so it's counted once after cross-group sum)
    if (gid == 0) {
        float e0 = asrc[i * H + head] + adst[i * H + head];
        e0 = e0 > 0.f ? e0 : 0.2f * e0;
        float w0 = __expf(e0);
        den = w0;
        float4 hv = hfeat4[(size_t)i * 64 + ch4];
        acc.x = w0 * hv.x; acc.y = w0 * hv.y; acc.z = w0 * hv.z; acc.w = w0 * hv.w;
    }

    int beg = rowptr[i], end = rowptr[i + 1];

    for (int p = beg; p < end; p += 32) {
        int cnt = min(32, end - p);
        __syncthreads();   // protects sh_src/sh_ex reuse, and first-iter sh_ad visibility
        if (tid < cnt) sh_src[tid] = colsrc[p + tid];
        __syncthreads();
        if (tid < cnt * H) {
            int j = tid / H, hd = tid % H;
            int s2 = sh_src[j];
            float ev = asrc[s2 * H + hd] + sh_ad[hd];
            ev = ev > 0.f ? ev : 0.2f * ev;
            sh_ex[j][hd] = __expf(ev);
        }
        __syncthreads();
        for (int j = gid; j < cnt; j += 4) {
            float w = sh_ex[j][head];
            float4 hv = hfeat4[(size_t)sh_src[j] * 64 + ch4];
            den += w;
            acc.x += w * hv.x; acc.y += w * hv.y; acc.z += w * hv.z; acc.w += w * hv.w;
        }
    }

    // cross-group combine
    __syncthreads();
    racc[gid][ch4] = acc;
    rden[gid][ch4] = den;
    __syncthreads();
    float4 at = racc[0][ch4];
    float4 a1 = racc[1][ch4], a2 = racc[2][ch4], a3 = racc[3][ch4];
    at.x += a1.x + a2.x + a3.x;
    at.y += a1.y + a2.y + a3.y;
    at.z += a1.z + a2.z + a3.z;
    at.w += a1.w + a2.w + a3.w;
    float dt = rden[0][ch4] + rden[1][ch4] + rden[2][ch4] + rden[3][ch4];

    float4 bv = bias4[ch4];
    float inv = 1.f / dt;
    float4 v = make_float4(at.x * inv + bv.x, at.y * inv + bv.y,
                           at.z * inv + bv.z, at.w * inv + bv.w);

    // LayerNorm over 256 channels (each channel held 4x across groups -> /1024)
    float mean = block_sum256(v.x + v.y + v.z + v.w, red) * (1.f / 1024.f);
    float4 dl = make_float4(v.x - mean, v.y - mean, v.z - mean, v.w - mean);
    float var = block_sum256(dl.x * dl.x + dl.y * dl.y + dl.z * dl.z + dl.w * dl.w, red)
                * (1.f / 1024.f);
    float rs = rsqrtf(var + 1e-5f);
    if (gid == 0) {
        float4 wv = lnw4[ch4];
        float4 bb = lnb4[ch4];
        float4 y;
        y.x = dl.x * rs * wv.x + bb.x;
        y.y = dl.y * rs * wv.y + bb.y;
        y.z = dl.z * rs * wv.z + bb.z;
        y.w = dl.w * rs * wv.w + bb.w;
        y.x = y.x > 0.f ? y.x : expm1f(y.x);
        y.y = y.y > 0.f ? y.y : expm1f(y.y);
        y.z = y.z > 0.f ? y.z : expm1f(y.z);
        y.w = y.w > 0.f ? y.w : expm1f(y.w);
        out4[(size_t)i * 64 + ch4] = y;
    }
}

// ---------------- launch ----------------------------------------------------
extern "C" void kernel_launch(void* const* d_in, const int* in_sizes, int n_in,
                              void* d_out, int out_size) {
    const float* x    = (const float*)d_in[0];
    const int*   ei   = (const int*)d_in[1];
    const float* W0   = (const float*)d_in[2];
    const float* as0  = (const float*)d_in[3];
    const float* ad0  = (const float*)d_in[4];
    const float* b0   = (const float*)d_in[5];
    const float* lnw0 = (const float*)d_in[6];
    const float* lnb0 = (const float*)d_in[7];
    const float* W1   = (const float*)d_in[8];
    const float* as1  = (const float*)d_in[9];
    const float* ad1  = (const float*)d_in[10];
    const float* b1   = (const float*)d_in[11];
    const float* lnw1 = (const float*)d_in[12];
    const float* lnb1 = (const float*)d_in[13];
    const float* W2   = (const float*)d_in[14];
    const float* as2  = (const float*)d_in[15];
    const float* ad2  = (const float*)d_in[16];
    const float* b2   = (const float*)d_in[17];
    const float* lnw2 = (const float*)d_in[18];
    const float* lnb2 = (const float*)d_in[19];
    float* out = (float*)d_out;

    int n = in_sizes[0] / 512;   // 50000
    int e = in_sizes[1] / 2;     // 800000
    const int* src = ei;
    const int* dst = ei + e;

    float *ph, *pbuf, *palpha;
    int *pcnt, *prow, *pcur, *pcol;
    cudaGetSymbolAddress((void**)&ph, g_h);
    cudaGetSymbolAddress((void**)&pbuf, g_buf);
    cudaGetSymbolAddress((void**)&palpha, g_alpha);
    cudaGetSymbolAddress((void**)&pcnt, g_cnt);
    cudaGetSymbolAddress((void**)&prow, g_rowptr);
    cudaGetSymbolAddress((void**)&pcur, g_cursor);
    cudaGetSymbolAddress((void**)&pcol, g_colsrc);

    float* pas0 = palpha + (size_t)0 * MAXN * 4;
    float* pad0 = palpha + (size_t)1 * MAXN * 4;
    float* pas1 = palpha + (size_t)2 * MAXN * 4;
    float* pad1 = palpha + (size_t)3 * MAXN * 4;
    float* pas2 = palpha + (size_t)4 * MAXN * 4;
    float* pad2 = palpha + (size_t)5 * MAXN * 4;

    const int TPB = 256;
    hist_kernel<<<(e + TPB - 1) / TPB, TPB>>>(dst, pcnt, palpha, e);
    scan_kernel<<<1, 1024>>>(pcnt, prow, pcur, n);
    scatter_kernel<<<(e + TPB - 1) / TPB, TPB>>>(src, dst, pcur, pcol, e);

    dim3 ggrid(NF / 128, (n + 127) / 128);

    // layer 0: GATConv(512 -> 4x64)
    gemm_tc<4><<<ggrid, 256>>>(x, W0, ph, n, 512, as0, ad0, pas0, pad0);
    agg_kernel<4><<<n, 256>>>((const float4*)ph, pas0, pad0, prow, pcol,
                              (const float4*)b0, (const float4*)lnw0,
                              (const float4*)lnb0, (float4*)pbuf);

    // layer 1: GATConv(256 -> 4x64)
    gemm_tc<4><<<ggrid, 256>>>(pbuf, W1, ph, n, 256, as1, ad1, pas1, pad1);
    agg_kernel<4><<<n, 256>>>((const float4*)ph, pas1, pad1, prow, pcol,
                              (const float4*)b1, (const float4*)lnw1,
                              (const float4*)lnb1, (float4*)pbuf);

    // layer 2: GATConv(256 -> 1x256)
    gemm_tc<1><<<ggrid, 256>>>(pbuf, W2, ph, n, 256, as2, ad2, pas2, pad2);
    agg_kernel<1><<<n, 256>>>((const float4*)ph, pas2, pad2, prow, pcol,
                              (const float4*)b2, (const float4*)lnw2,
                              (const float4*)lnb2, (float4*)out);
}

// round 7
// speedup vs baseline: 1.3525x; 1.3525x over previous
#include <cuda_runtime.h>
#include <stdint.h>
#include <math.h>

#define MAXN 50000
#define MAXE 800000
#define NF 256

// ---------------- scratch (device globals; no allocation allowed) ----------
__device__ float g_h[(size_t)MAXN * NF];     // GEMM output (pre-aggregation features)
__device__ float g_buf[(size_t)MAXN * NF];   // layer output (post LN+ELU) = next layer input
// per-layer alpha buffers: [layer][asrc|adst][MAXN*4]
__device__ float g_alpha[(size_t)6 * MAXN * 4];
__device__ float g_wexp[(size_t)MAXE * 4];   // per-edge softmax numerators (CSR order)
__device__ int   g_cnt[MAXN];                // zero-initialized; scan re-zeroes for next call
__device__ int   g_rowptr[MAXN + 1];
__device__ int   g_cursor[MAXN];
__device__ int   g_colsrc[MAXE];
__device__ int   g_coldst[MAXE];

// ---------------- CSR build ------------------------------------------------
__global__ void hist_kernel(const int* __restrict__ dst, int* __restrict__ cnt,
                            float* __restrict__ alpha, int e) {
    int t = blockIdx.x * blockDim.x + threadIdx.x;
    if (t < e) atomicAdd(&cnt[dst[t]], 1);
    const int total = 6 * MAXN * 4;
    for (int i = t; i < total; i += gridDim.x * blockDim.x) alpha[i] = 0.f;
}

__global__ void scan_kernel(int* __restrict__ cnt, int* __restrict__ rowptr,
                            int* __restrict__ cursor, int n) {
    __shared__ int sh[1024];
    int tid = threadIdx.x;
    int chunk = (n + 1023) >> 10;
    int base = tid * chunk;
    int s = 0;
    for (int j = 0; j < chunk; j++) {
        int idx = base + j;
        if (idx < n) s += cnt[idx];
    }
    sh[tid] = s;
    __syncthreads();
    for (int off = 1; off < 1024; off <<= 1) {
        int v = (tid >= off) ? sh[tid - off] : 0;
        __syncthreads();
        sh[tid] += v;
        __syncthreads();
    }
    int run = sh[tid] - s;  // exclusive prefix
    for (int j = 0; j < chunk; j++) {
        int idx = base + j;
        if (idx < n) {
            rowptr[idx] = run;
            cursor[idx] = run;
            run += cnt[idx];
            cnt[idx] = 0;   // re-zero for next graph replay
        }
    }
    if (tid == 1023) rowptr[n] = run;
}

__global__ void scatter_kernel(const int* __restrict__ src, const int* __restrict__ dst,
                               int* __restrict__ cursor, int* __restrict__ colsrc,
                               int* __restrict__ coldst, int e) {
    int t = blockIdx.x * blockDim.x + threadIdx.x;
    if (t < e) {
        int d = dst[t];
        int p = atomicAdd(&cursor[d], 1);
        colsrc[p] = src[t];
        coldst[p] = d;
    }
}

// ---------------- per-edge softmax numerators (CSR order) -------------------
template <int H>
__global__ void weight_kernel(const float* __restrict__ asrc, const float* __restrict__ adst,
                              const int* __restrict__ colsrc, const int* __restrict__ coldst,
                              float* __restrict__ wexp, int e) {
    int t = blockIdx.x * blockDim.x + threadIdx.x;
    if (t < e) {
        int s = colsrc[t], d = coldst[t];
#pragma unroll
        for (int h = 0; h < H; h++) {
            float ev = asrc[s * H + h] + adst[d * H + h];
            ev = ev > 0.f ? ev : 0.2f * ev;
            wexp[t * H + h] = __expf(ev);
        }
    }
}

// ---------------- tf32 helpers ----------------------------------------------
__device__ __forceinline__ float tf32_rna(float x) {
    uint32_t u;
    asm("cvt.rna.tf32.f32 %0, %1;" : "=r"(u) : "f"(x));
    return __uint_as_float(u);
}

__device__ __forceinline__ void mma_tf32(float c[4],
                                         uint32_t a0, uint32_t a1, uint32_t a2, uint32_t a3,
                                         uint32_t b0, uint32_t b1) {
    asm volatile(
        "mma.sync.aligned.m16n8k8.row.col.f32.tf32.tf32.f32 "
        "{%0,%1,%2,%3}, {%4,%5,%6,%7}, {%8,%9}, {%0,%1,%2,%3};"
        : "+f"(c[0]), "+f"(c[1]), "+f"(c[2]), "+f"(c[3])
        : "r"(a0), "r"(a1), "r"(a2), "r"(a3), "r"(b0), "r"(b1));
}

// ---------------- tensor-core GEMM + fused alpha projection -----------------
template <int H>
__global__ void __launch_bounds__(256, 2) gemm_tc(
    const float* __restrict__ A, const float* __restrict__ B,
    float* __restrict__ C, int M, int K,
    const float* __restrict__ a_s, const float* __restrict__ a_d,
    float* __restrict__ asrc, float* __restrict__ adst)
{
    __shared__ float4 As_hi4[128 * 5];   // 128 rows x 20 floats
    __shared__ float4 As_lo4[128 * 5];
    __shared__ float4 Bs_hi4[16 * 34];   // 16 k-rows x 136 floats
    __shared__ float4 Bs_lo4[16 * 34];
    const float* As_hi = (const float*)As_hi4;
    const float* As_lo = (const float*)As_lo4;
    const float* Bs_hi = (const float*)Bs_hi4;
    const float* Bs_lo = (const float*)Bs_lo4;

    const int tid  = threadIdx.x;
    const int lane = tid & 31;
    const int w    = tid >> 5;
    const int g    = lane >> 2;
    const int t    = lane & 3;
    const int wm   = w >> 2;
    const int wn   = w & 3;

    const int row0 = blockIdx.y * 128;
    const int col0 = blockIdx.x * 128;

    const int ar0 = tid >> 2;
    const int ar1 = 64 + (tid >> 2);
    const int ac4 = tid & 3;
    const int bk0 = tid >> 5;
    const int bk1 = 8 + (tid >> 5);
    const int bc4 = tid & 31;

    const bool ok0 = (row0 + ar0) < M;
    const bool ok1 = (row0 + ar1) < M;

    float acc[4][4][4];
#pragma unroll
    for (int mt = 0; mt < 4; mt++)
#pragma unroll
        for (int nt = 0; nt < 4; nt++)
#pragma unroll
            for (int i = 0; i < 4; i++) acc[mt][nt][i] = 0.f;

    const float4 z4 = make_float4(0.f, 0.f, 0.f, 0.f);
    float4 pa0, pa1, pb0, pb1;

    pa0 = ok0 ? *(const float4*)(A + (size_t)(row0 + ar0) * K + ac4 * 4) : z4;
    pa1 = ok1 ? *(const float4*)(A + (size_t)(row0 + ar1) * K + ac4 * 4) : z4;
    pb0 = *(const float4*)(B + (size_t)bk0 * NF + col0 + bc4 * 4);
    pb1 = *(const float4*)(B + (size_t)bk1 * NF + col0 + bc4 * 4);

    for (int kt = 0; kt < K; kt += 16) {
        {
            float4 h, l;
            h.x = tf32_rna(pa0.x); l.x = tf32_rna(pa0.x - h.x);
            h.y = tf32_rna(pa0.y); l.y = tf32_rna(pa0.y - h.y);
            h.z = tf32_rna(pa0.z); l.z = tf32_rna(pa0.z - h.z);
            h.w = tf32_rna(pa0.w); l.w = tf32_rna(pa0.w - h.w);
            As_hi4[ar0 * 5 + ac4] = h; As_lo4[ar0 * 5 + ac4] = l;
            h.x = tf32_rna(pa1.x); l.x = tf32_rna(pa1.x - h.x);
            h.y = tf32_rna(pa1.y); l.y = tf32_rna(pa1.y - h.y);
            h.z = tf32_rna(pa1.z); l.z = tf32_rna(pa1.z - h.z);
            h.w = tf32_rna(pa1.w); l.w = tf32_rna(pa1.w - h.w);
            As_hi4[ar1 * 5 + ac4] = h; As_lo4[ar1 * 5 + ac4] = l;
            h.x = tf32_rna(pb0.x); l.x = tf32_rna(pb0.x - h.x);
            h.y = tf32_rna(pb0.y); l.y = tf32_rna(pb0.y - h.y);
            h.z = tf32_rna(pb0.z); l.z = tf32_rna(pb0.z - h.z);
            h.w = tf32_rna(pb0.w); l.w = tf32_rna(pb0.w - h.w);
            Bs_hi4[bk0 * 34 + bc4] = h; Bs_lo4[bk0 * 34 + bc4] = l;
            h.x = tf32_rna(pb1.x); l.x = tf32_rna(pb1.x - h.x);
            h.y = tf32_rna(pb1.y); l.y = tf32_rna(pb1.y - h.y);
            h.z = tf32_rna(pb1.z); l.z = tf32_rna(pb1.z - h.z);
            h.w = tf32_rna(pb1.w); l.w = tf32_rna(pb1.w - h.w);
            Bs_hi4[bk1 * 34 + bc4] = h; Bs_lo4[bk1 * 34 + bc4] = l;
        }
        __syncthreads();

        int ktn = kt + 16;
        if (ktn < K) {
            pa0 = ok0 ? *(const float4*)(A + (size_t)(row0 + ar0) * K + ktn + ac4 * 4) : z4;
            pa1 = ok1 ? *(const float4*)(A + (size_t)(row0 + ar1) * K + ktn + ac4 * 4) : z4;
            pb0 = *(const float4*)(B + (size_t)(ktn + bk0) * NF + col0 + bc4 * 4);
            pb1 = *(const float4*)(B + (size_t)(ktn + bk1) * NF + col0 + bc4 * 4);
        }

#pragma unroll
        for (int kk = 0; kk < 16; kk += 8) {
            uint32_t bh[4][2], bl[4][2];
            const int cb = wn * 32;
#pragma unroll
            for (int nt = 0; nt < 4; nt++) {
                int col = cb + nt * 8 + g;
                bh[nt][0] = __float_as_uint(Bs_hi[(kk + t) * 136 + col]);
                bh[nt][1] = __float_as_uint(Bs_hi[(kk + t + 4) * 136 + col]);
                bl[nt][0] = __float_as_uint(Bs_lo[(kk + t) * 136 + col]);
                bl[nt][1] = __float_as_uint(Bs_lo[(kk + t + 4) * 136 + col]);
            }
#pragma unroll
            for (int mt = 0; mt < 4; mt++) {
                int rb = wm * 64 + mt * 16 + g;
                uint32_t ah[4], al[4];
                ah[0] = __float_as_uint(As_hi[rb * 20 + kk + t]);
                ah[1] = __float_as_uint(As_hi[(rb + 8) * 20 + kk + t]);
                ah[2] = __float_as_uint(As_hi[rb * 20 + kk + t + 4]);
                ah[3] = __float_as_uint(As_hi[(rb + 8) * 20 + kk + t + 4]);
                al[0] = __float_as_uint(As_lo[rb * 20 + kk + t]);
                al[1] = __float_as_uint(As_lo[(rb + 8) * 20 + kk + t]);
                al[2] = __float_as_uint(As_lo[rb * 20 + kk + t + 4]);
                al[3] = __float_as_uint(As_lo[(rb + 8) * 20 + kk + t + 4]);
#pragma unroll
                for (int nt = 0; nt < 4; nt++) {
                    mma_tf32(acc[mt][nt], ah[0], ah[1], ah[2], ah[3], bh[nt][0], bh[nt][1]);
                    mma_tf32(acc[mt][nt], ah[0], ah[1], ah[2], ah[3], bl[nt][0], bl[nt][1]);
                    mma_tf32(acc[mt][nt], al[0], al[1], al[2], al[3], bh[nt][0], bh[nt][1]);
                }
            }
        }
        __syncthreads();
    }

    // ---- epilogue 1: store C tile ----
#pragma unroll
    for (int mt = 0; mt < 4; mt++) {
        int r0 = row0 + wm * 64 + mt * 16 + g;
        int r1 = r0 + 8;
#pragma unroll
        for (int nt = 0; nt < 4; nt++) {
            int col = col0 + wn * 32 + nt * 8 + 2 * t;
            if (r0 < M)
                *(float2*)(C + (size_t)r0 * NF + col) = make_float2(acc[mt][nt][0], acc[mt][nt][1]);
            if (r1 < M)
                *(float2*)(C + (size_t)r1 * NF + col) = make_float2(acc[mt][nt][2], acc[mt][nt][3]);
        }
    }

    // ---- epilogue 2: fused alpha projection ----
    {
        float asv[4][2], adv[4][2];
#pragma unroll
        for (int nt = 0; nt < 4; nt++)
#pragma unroll
            for (int i = 0; i < 2; i++) {
                int gcol = col0 + wn * 32 + nt * 8 + 2 * t + i;
                asv[nt][i] = a_s[gcol];
                adv[nt][i] = a_d[gcol];
            }
        const int hd = (H == 4) ? ((col0 + wn * 32) >> 6) : 0;
#pragma unroll
        for (int mt = 0; mt < 4; mt++) {
            float sa0 = 0.f, sd0 = 0.f, sa1 = 0.f, sd1 = 0.f;
#pragma unroll
            for (int nt = 0; nt < 4; nt++)
#pragma unroll
                for (int i = 0; i < 2; i++) {
                    sa0 += acc[mt][nt][i]     * asv[nt][i];
                    sd0 += acc[mt][nt][i]     * adv[nt][i];
                    sa1 += acc[mt][nt][2 + i] * asv[nt][i];
                    sd1 += acc[mt][nt][2 + i] * adv[nt][i];
                }
#pragma unroll
            for (int o = 1; o <= 2; o <<= 1) {
                sa0 += __shfl_xor_sync(0xffffffffu, sa0, o);
                sd0 += __shfl_xor_sync(0xffffffffu, sd0, o);
                sa1 += __shfl_xor_sync(0xffffffffu, sa1, o);
                sd1 += __shfl_xor_sync(0xffffffffu, sd1, o);
            }
            if (t == 0) {
                int r0 = row0 + wm * 64 + mt * 16 + g;
                int r1 = r0 + 8;
                if (r0 < M) {
                    atomicAdd(&asrc[r0 * H + hd], sa0);
                    atomicAdd(&adst[r0 * H + hd], sd0);
                }
                if (r1 < M) {
                    atomicAdd(&asrc[r1 * H + hd], sa1);
                    atomicAdd(&adst[r1 * H + hd], sd1);
                }
            }
        }
    }
}

// ---------------- block-sum helper (64 threads, 2 warps) ---------------------
__device__ __forceinline__ float block_sum64(float v, float* red) {
#pragma unroll
    for (int o = 16; o > 0; o >>= 1) v += __shfl_xor_sync(0xffffffffu, v, o);
    int wid = threadIdx.x >> 5;
    if ((threadIdx.x & 31) == 0) red[wid] = v;
    __syncthreads();
    float s = red[0] + red[1];
    __syncthreads();
    return s;
}

// ---------------- fused aggregation + bias + LN + ELU -----------------------
// One 64-thread block per destination node; edge weights precomputed, so the
// gather loop is barrier-free and unrolled x4 for MLP.
template <int H>
__global__ void __launch_bounds__(64) agg_kernel(
    const float4* __restrict__ hfeat4,
    const float* __restrict__ asrc, const float* __restrict__ adst,
    const int* __restrict__ rowptr, const int* __restrict__ colsrc,
    const float* __restrict__ wexp,
    const float4* __restrict__ bias4, const float4* __restrict__ lnw4,
    const float4* __restrict__ lnb4, float4* __restrict__ out4)
{
    __shared__ float red[2];

    int i   = blockIdx.x;
    int tid = threadIdx.x;                 // float4 channel 0..63
    int head = (H == 4) ? (tid >> 4) : 0;

    // self-loop (PyG add_self_loops=True)
    float e0 = asrc[i * H + head] + adst[i * H + head];
    e0 = e0 > 0.f ? e0 : 0.2f * e0;
    float w0 = __expf(e0);
    float den = w0;
    float4 hv = hfeat4[(size_t)i * 64 + tid];
    float4 acc = make_float4(w0 * hv.x, w0 * hv.y, w0 * hv.z, w0 * hv.w);

    int beg = rowptr[i], end = rowptr[i + 1];
    int p = beg;
    for (; p + 4 <= end; p += 4) {
        int s0 = colsrc[p], s1 = colsrc[p + 1], s2 = colsrc[p + 2], s3 = colsrc[p + 3];
        float w_0 = wexp[(p + 0) * H + head];
        float w_1 = wexp[(p + 1) * H + head];
        float w_2 = wexp[(p + 2) * H + head];
        float w_3 = wexp[(p + 3) * H + head];
        float4 h0 = hfeat4[(size_t)s0 * 64 + tid];
        float4 h1 = hfeat4[(size_t)s1 * 64 + tid];
        float4 h2 = hfeat4[(size_t)s2 * 64 + tid];
        float4 h3 = hfeat4[(size_t)s3 * 64 + tid];
        den += (w_0 + w_1) + (w_2 + w_3);
        acc.x += w_0 * h0.x + w_1 * h1.x + w_2 * h2.x + w_3 * h3.x;
        acc.y += w_0 * h0.y + w_1 * h1.y + w_2 * h2.y + w_3 * h3.y;
        acc.z += w_0 * h0.z + w_1 * h1.z + w_2 * h2.z + w_3 * h3.z;
        acc.w += w_0 * h0.w + w_1 * h1.w + w_2 * h2.w + w_3 * h3.w;
    }
    for (; p < end; p++) {
        int s0 = colsrc[p];
        float wv = wexp[p * H + head];
        float4 h0 = hfeat4[(size_t)s0 * 64 + tid];
        den += wv;
        acc.x += wv * h0.x; acc.y += wv * h0.y; acc.z += wv * h0.z; acc.w += wv * h0.w;
    }

    float4 bv = bias4[tid];
    float inv = 1.f / den;
    float4 v = make_float4(acc.x * inv + bv.x, acc.y * inv + bv.y,
                           acc.z * inv + bv.z, acc.w * inv + bv.w);

    // LayerNorm over 256 channels (64 threads x 4 channels)
    float mean = block_sum64(v.x + v.y + v.z + v.w, red) * (1.f / NF);
    float4 dl = make_float4(v.x - mean, v.y - mean, v.z - mean, v.w - mean);
    float var = block_sum64(dl.x * dl.x + dl.y * dl.y + dl.z * dl.z + dl.w * dl.w, red)
                * (1.f / NF);
    float rs = rsqrtf(var + 1e-5f);
    float4 wv4 = lnw4[tid];
    float4 bb = lnb4[tid];
    float4 y;
    y.x = dl.x * rs * wv4.x + bb.x;
    y.y = dl.y * rs * wv4.y + bb.y;
    y.z = dl.z * rs * wv4.z + bb.z;
    y.w = dl.w * rs * wv4.w + bb.w;
    y.x = y.x > 0.f ? y.x : expm1f(y.x);
    y.y = y.y > 0.f ? y.y : expm1f(y.y);
    y.z = y.z > 0.f ? y.z : expm1f(y.z);
    y.w = y.w > 0.f ? y.w : expm1f(y.w);
    out4[(size_t)i * 64 + tid] = y;
}

// ---------------- launch ----------------------------------------------------
extern "C" void kernel_launch(void* const* d_in, const int* in_sizes, int n_in,
                              void* d_out, int out_size) {
    const float* x    = (const float*)d_in[0];
    const int*   ei   = (const int*)d_in[1];
    const float* W0   = (const float*)d_in[2];
    const float* as0  = (const float*)d_in[3];
    const float* ad0  = (const float*)d_in[4];
    const float* b0   = (const float*)d_in[5];
    const float* lnw0 = (const float*)d_in[6];
    const float* lnb0 = (const float*)d_in[7];
    const float* W1   = (const float*)d_in[8];
    const float* as1  = (const float*)d_in[9];
    const float* ad1  = (const float*)d_in[10];
    const float* b1   = (const float*)d_in[11];
    const float* lnw1 = (const float*)d_in[12];
    const float* lnb1 = (const float*)d_in[13];
    const float* W2   = (const float*)d_in[14];
    const float* as2  = (const float*)d_in[15];
    const float* ad2  = (const float*)d_in[16];
    const float* b2   = (const float*)d_in[17];
    const float* lnw2 = (const float*)d_in[18];
    const float* lnb2 = (const float*)d_in[19];
    float* out = (float*)d_out;

    int n = in_sizes[0] / 512;   // 50000
    int e = in_sizes[1] / 2;     // 800000
    const int* src = ei;
    const int* dst = ei + e;

    float *ph, *pbuf, *palpha, *pwexp;
    int *pcnt, *prow, *pcur, *pcol, *pcds;
    cudaGetSymbolAddress((void**)&ph, g_h);
    cudaGetSymbolAddress((void**)&pbuf, g_buf);
    cudaGetSymbolAddress((void**)&palpha, g_alpha);
    cudaGetSymbolAddress((void**)&pwexp, g_wexp);
    cudaGetSymbolAddress((void**)&pcnt, g_cnt);
    cudaGetSymbolAddress((void**)&prow, g_rowptr);
    cudaGetSymbolAddress((void**)&pcur, g_cursor);
    cudaGetSymbolAddress((void**)&pcol, g_colsrc);
    cudaGetSymbolAddress((void**)&pcds, g_coldst);

    float* pas0 = palpha + (size_t)0 * MAXN * 4;
    float* pad0 = palpha + (size_t)1 * MAXN * 4;
    float* pas1 = palpha + (size_t)2 * MAXN * 4;
    float* pad1 = palpha + (size_t)3 * MAXN * 4;
    float* pas2 = palpha + (size_t)4 * MAXN * 4;
    float* pad2 = palpha + (size_t)5 * MAXN * 4;

    const int TPB = 256;
    const int egrid = (e + TPB - 1) / TPB;
    hist_kernel<<<egrid, TPB>>>(dst, pcnt, palpha, e);
    scan_kernel<<<1, 1024>>>(pcnt, prow, pcur, n);
    scatter_kernel<<<egrid, TPB>>>(src, dst, pcur, pcol, pcds, e);

    dim3 ggrid(NF / 128, (n + 127) / 128);

    // layer 0: GATConv(512 -> 4x64)
    gemm_tc<4><<<ggrid, 256>>>(x, W0, ph, n, 512, as0, ad0, pas0, pad0);
    weight_kernel<4><<<egrid, TPB>>>(pas0, pad0, pcol, pcds, pwexp, e);
    agg_kernel<4><<<n, 64>>>((const float4*)ph, pas0, pad0, prow, pcol, pwexp,
                             (const float4*)b0, (const float4*)lnw0,
                             (const float4*)lnb0, (float4*)pbuf);

    // layer 1: GATConv(256 -> 4x64)
    gemm_tc<4><<<ggrid, 256>>>(pbuf, W1, ph, n, 256, as1, ad1, pas1, pad1);
    weight_kernel<4><<<egrid, TPB>>>(pas1, pad1, pcol, pcds, pwexp, e);
    agg_kernel<4><<<n, 64>>>((const float4*)ph, pas1, pad1, prow, pcol, pwexp,
                             (const float4*)b1, (const float4*)lnw1,
                             (const float4*)lnb1, (float4*)pbuf);

    // layer 2: GATConv(256 -> 1x256)
    gemm_tc<1><<<ggrid, 256>>>(pbuf, W2, ph, n, 256, as2, ad2, pas2, pad2);
    weight_kernel<1><<<egrid, TPB>>>(pas2, pad2, pcol, pcds, pwexp, e);
    agg_kernel<1><<<n, 64>>>((const float4*)ph, pas2, pad2, prow, pcol, pwexp,
                             (const float4*)b2, (const float4*)lnw2,
                             (const float4*)lnb2, (float4*)out);
}

// round 8
// speedup vs baseline: 1.4965x; 1.1064x over previous
#include <cuda_runtime.h>
#include <cuda_bf16.h>
#include <stdint.h>
#include <math.h>

#define MAXN 50000
#define MAXE 800000
#define NF 256

// ---------------- scratch (device globals; no allocation allowed) ----------
__device__ float g_h[(size_t)MAXN * NF];     // GEMM output (pre-aggregation features)
__device__ float g_buf[(size_t)MAXN * NF];   // layer output (post LN+ELU) = next layer input
__device__ float g_alpha[(size_t)6 * MAXN * 4];
__device__ float g_wexp[(size_t)MAXE * 4];   // per-edge softmax numerators (CSR order)
__device__ int   g_cnt[MAXN];
__device__ int   g_rowptr[MAXN + 1];
__device__ int   g_cursor[MAXN];
__device__ int   g_colsrc[MAXE];
__device__ int   g_coldst[MAXE];
// pre-transposed, bf16-split weights: [n][kpair] packed bf16x2
__device__ uint32_t g_w0h[256 * 256], g_w0l[256 * 256];   // W0: K=512 -> 256 kpairs
__device__ uint32_t g_w1h[256 * 128], g_w1l[256 * 128];   // W1: K=256 -> 128 kpairs
__device__ uint32_t g_w2h[256 * 128], g_w2l[256 * 128];   // W2

// ---------------- helpers ----------------------------------------------------
__device__ __forceinline__ uint32_t bf16_pack_hi(float f0, float f1) {
    __nv_bfloat16 h0 = __float2bfloat16(f0);
    __nv_bfloat16 h1 = __float2bfloat16(f1);
    return (uint32_t)__bfloat16_as_ushort(h0) | ((uint32_t)__bfloat16_as_ushort(h1) << 16);
}
__device__ __forceinline__ uint32_t bf16_pack_lo(float f0, float f1) {
    __nv_bfloat16 h0 = __float2bfloat16(f0);
    __nv_bfloat16 h1 = __float2bfloat16(f1);
    __nv_bfloat16 l0 = __float2bfloat16(f0 - __bfloat162float(h0));
    __nv_bfloat16 l1 = __float2bfloat16(f1 - __bfloat162float(h1));
    return (uint32_t)__bfloat16_as_ushort(l0) | ((uint32_t)__bfloat16_as_ushort(l1) << 16);
}

__device__ __forceinline__ void mma_bf16(float c[4],
                                         uint32_t a0, uint32_t a1, uint32_t a2, uint32_t a3,
                                         uint32_t b0, uint32_t b1) {
    asm volatile(
        "mma.sync.aligned.m16n8k16.row.col.f32.bf16.bf16.f32 "
        "{%0,%1,%2,%3}, {%4,%5,%6,%7}, {%8,%9}, {%0,%1,%2,%3};"
        : "+f"(c[0]), "+f"(c[1]), "+f"(c[2]), "+f"(c[3])
        : "r"(a0), "r"(a1), "r"(a2), "r"(a3), "r"(b0), "r"(b1));
}

// ---------------- weight prep: transpose + bf16-split all three Ws ----------
__global__ void prep_w_kernel(const float* __restrict__ W0, const float* __restrict__ W1,
                              const float* __restrict__ W2,
                              uint32_t* __restrict__ w0h, uint32_t* __restrict__ w0l,
                              uint32_t* __restrict__ w1h, uint32_t* __restrict__ w1l,
                              uint32_t* __restrict__ w2h, uint32_t* __restrict__ w2l) {
    int t = blockIdx.x * blockDim.x + threadIdx.x;
    const int T0 = 256 * 256, T1 = 256 * 128;
    if (t < T0) {
        int n = t >> 8, kp = t & 255;
        float f0 = W0[(2 * kp) * 256 + n];
        float f1 = W0[(2 * kp + 1) * 256 + n];
        w0h[n * 256 + kp] = bf16_pack_hi(f0, f1);
        w0l[n * 256 + kp] = bf16_pack_lo(f0, f1);
    } else if (t < T0 + T1) {
        int id = t - T0;
        int n = id >> 7, kp = id & 127;
        float f0 = W1[(2 * kp) * 256 + n];
        float f1 = W1[(2 * kp + 1) * 256 + n];
        w1h[n * 128 + kp] = bf16_pack_hi(f0, f1);
        w1l[n * 128 + kp] = bf16_pack_lo(f0, f1);
    } else if (t < T0 + 2 * T1) {
        int id = t - T0 - T1;
        int n = id >> 7, kp = id & 127;
        float f0 = W2[(2 * kp) * 256 + n];
        float f1 = W2[(2 * kp + 1) * 256 + n];
        w2h[n * 128 + kp] = bf16_pack_hi(f0, f1);
        w2l[n * 128 + kp] = bf16_pack_lo(f0, f1);
    }
}

// ---------------- CSR build ------------------------------------------------
__global__ void hist_kernel(const int* __restrict__ dst, int* __restrict__ cnt,
                            float* __restrict__ alpha, int e) {
    int t = blockIdx.x * blockDim.x + threadIdx.x;
    if (t < e) atomicAdd(&cnt[dst[t]], 1);
    const int total = 6 * MAXN * 4;
    for (int i = t; i < total; i += gridDim.x * blockDim.x) alpha[i] = 0.f;
}

__global__ void scan_kernel(int* __restrict__ cnt, int* __restrict__ rowptr,
                            int* __restrict__ cursor, int n) {
    __shared__ int sh[1024];
    int tid = threadIdx.x;
    int chunk = (n + 1023) >> 10;
    int base = tid * chunk;
    int s = 0;
    for (int j = 0; j < chunk; j++) {
        int idx = base + j;
        if (idx < n) s += cnt[idx];
    }
    sh[tid] = s;
    __syncthreads();
    for (int off = 1; off < 1024; off <<= 1) {
        int v = (tid >= off) ? sh[tid - off] : 0;
        __syncthreads();
        sh[tid] += v;
        __syncthreads();
    }
    int run = sh[tid] - s;
    for (int j = 0; j < chunk; j++) {
        int idx = base + j;
        if (idx < n) {
            rowptr[idx] = run;
            cursor[idx] = run;
            run += cnt[idx];
            cnt[idx] = 0;
        }
    }
    if (tid == 1023) rowptr[n] = run;
}

__global__ void scatter_kernel(const int* __restrict__ src, const int* __restrict__ dst,
                               int* __restrict__ cursor, int* __restrict__ colsrc,
                               int* __restrict__ coldst, int e) {
    int t = blockIdx.x * blockDim.x + threadIdx.x;
    if (t < e) {
        int d = dst[t];
        int p = atomicAdd(&cursor[d], 1);
        colsrc[p] = src[t];
        coldst[p] = d;
    }
}

// ---------------- per-edge softmax numerators (CSR order) -------------------
template <int H>
__global__ void weight_kernel(const float* __restrict__ asrc, const float* __restrict__ adst,
                              const int* __restrict__ colsrc, const int* __restrict__ coldst,
                              float* __restrict__ wexp, int e) {
    int t = blockIdx.x * blockDim.x + threadIdx.x;
    if (t < e) {
        int s = colsrc[t], d = coldst[t];
#pragma unroll
        for (int h = 0; h < H; h++) {
            float ev = asrc[s * H + h] + adst[d * H + h];
            ev = ev > 0.f ? ev : 0.2f * ev;
            wexp[t * H + h] = __expf(ev);
        }
    }
}

// ---------------- bf16x3 tensor-core GEMM + fused alpha projection ----------
// C[M,256] = A[M,K] @ B[K,256]; B pre-transposed/split as [n][kpair] bf16x2.
// 128x128 CTA tile, BK=32, 8 warps (2x4), warp tile 64x32, m16n8k16 bf16 mma
// 3-term split (hi*hi + hi*lo + lo*hi).
// Shared: uint32 [row/n][20] (16 kpairs + 4 pad) -> conflict-free frags.
template <int H>
__global__ void __launch_bounds__(256, 2) gemm_bf16(
    const float* __restrict__ A,
    const uint32_t* __restrict__ Bth, const uint32_t* __restrict__ Btl,
    float* __restrict__ C, int M, int K,
    const float* __restrict__ a_s, const float* __restrict__ a_d,
    float* __restrict__ asrc, float* __restrict__ adst)
{
    __shared__ uint32_t Ah[128 * 20];
    __shared__ uint32_t Al[128 * 20];
    __shared__ uint32_t Bh[128 * 20];
    __shared__ uint32_t Bl[128 * 20];

    const int tid  = threadIdx.x;
    const int lane = tid & 31;
    const int w    = tid >> 5;
    const int g    = lane >> 2;
    const int t    = lane & 3;
    const int wm   = w >> 2;
    const int wn   = w & 3;

    const int row0 = blockIdx.y * 128;
    const int col0 = blockIdx.x * 128;
    const int KW   = K >> 1;              // kpairs per row of Bt

    // staging indices
    const int ar  = tid >> 1;             // A row 0..127
    const int ak16 = (tid & 1) << 4;      // A k base within tile: 0 or 16
    const int bn  = tid >> 1;             // B n 0..127
    const int bk8 = (tid & 1) << 3;       // B kpair base: 0 or 8

    const bool a_ok = (row0 + ar) < M;
    const float* Arow = A + (size_t)(row0 + ar) * K + ak16;
    const uint32_t* Bhrow = Bth + (size_t)(col0 + bn) * KW + bk8;
    const uint32_t* Blrow = Btl + (size_t)(col0 + bn) * KW + bk8;

    float acc[4][4][4];
#pragma unroll
    for (int mt = 0; mt < 4; mt++)
#pragma unroll
        for (int nt = 0; nt < 4; nt++)
#pragma unroll
            for (int i = 0; i < 4; i++) acc[mt][nt][i] = 0.f;

    const float4 z4 = make_float4(0.f, 0.f, 0.f, 0.f);
    float4 pa[4];
    uint4  pbh0, pbh1, pbl0, pbl1;

    // prefetch tile 0
#pragma unroll
    for (int i = 0; i < 4; i++)
        pa[i] = a_ok ? *(const float4*)(Arow + i * 4) : z4;
    pbh0 = *(const uint4*)(Bhrow);
    pbh1 = *(const uint4*)(Bhrow + 4);
    pbl0 = *(const uint4*)(Blrow);
    pbl1 = *(const uint4*)(Blrow + 4);

    for (int kt = 0; kt < K; kt += 32) {
        // ---- convert/store staged tile ----
        {
            uint32_t wh[8], wl[8];
#pragma unroll
            for (int i = 0; i < 4; i++) {
                wh[2 * i]     = bf16_pack_hi(pa[i].x, pa[i].y);
                wh[2 * i + 1] = bf16_pack_hi(pa[i].z, pa[i].w);
                wl[2 * i]     = bf16_pack_lo(pa[i].x, pa[i].y);
                wl[2 * i + 1] = bf16_pack_lo(pa[i].z, pa[i].w);
            }
            uint32_t* pA = &Ah[ar * 20 + (ak16 >> 1)];
            uint32_t* pAl = &Al[ar * 20 + (ak16 >> 1)];
            *(uint4*)(pA)      = make_uint4(wh[0], wh[1], wh[2], wh[3]);
            *(uint4*)(pA + 4)  = make_uint4(wh[4], wh[5], wh[6], wh[7]);
            *(uint4*)(pAl)     = make_uint4(wl[0], wl[1], wl[2], wl[3]);
            *(uint4*)(pAl + 4) = make_uint4(wl[4], wl[5], wl[6], wl[7]);
            uint32_t* pB  = &Bh[bn * 20 + bk8];
            uint32_t* pBl = &Bl[bn * 20 + bk8];
            *(uint4*)(pB)      = pbh0;
            *(uint4*)(pB + 4)  = pbh1;
            *(uint4*)(pBl)     = pbl0;
            *(uint4*)(pBl + 4) = pbl1;
        }
        __syncthreads();

        // ---- prefetch next tile ----
        int ktn = kt + 32;
        if (ktn < K) {
#pragma unroll
            for (int i = 0; i < 4; i++)
                pa[i] = a_ok ? *(const float4*)(Arow + ktn + i * 4) : z4;
            int kwn = ktn >> 1;
            pbh0 = *(const uint4*)(Bhrow + kwn);
            pbh1 = *(const uint4*)(Bhrow + kwn + 4);
            pbl0 = *(const uint4*)(Blrow + kwn);
            pbl1 = *(const uint4*)(Blrow + kwn + 4);
        }

        // ---- mma: 2 k-steps of 16 ----
#pragma unroll
        for (int kk = 0; kk < 2; kk++) {
            const int kb = kk * 8 + t;
            uint32_t bh[4][2], bl[4][2];
#pragma unroll
            for (int nt = 0; nt < 4; nt++) {
                int n = wn * 32 + nt * 8 + g;
                bh[nt][0] = Bh[n * 20 + kb];
                bh[nt][1] = Bh[n * 20 + kb + 4];
                bl[nt][0] = Bl[n * 20 + kb];
                bl[nt][1] = Bl[n * 20 + kb + 4];
            }
#pragma unroll
            for (int mt = 0; mt < 4; mt++) {
                int rb = wm * 64 + mt * 16 + g;
                uint32_t ah[4], al[4];
                ah[0] = Ah[rb * 20 + kb];
                ah[1] = Ah[(rb + 8) * 20 + kb];
                ah[2] = Ah[rb * 20 + kb + 4];
                ah[3] = Ah[(rb + 8) * 20 + kb + 4];
                al[0] = Al[rb * 20 + kb];
                al[1] = Al[(rb + 8) * 20 + kb];
                al[2] = Al[rb * 20 + kb + 4];
                al[3] = Al[(rb + 8) * 20 + kb + 4];
#pragma unroll
                for (int nt = 0; nt < 4; nt++) {
                    mma_bf16(acc[mt][nt], ah[0], ah[1], ah[2], ah[3], bh[nt][0], bh[nt][1]);
                    mma_bf16(acc[mt][nt], ah[0], ah[1], ah[2], ah[3], bl[nt][0], bl[nt][1]);
                    mma_bf16(acc[mt][nt], al[0], al[1], al[2], al[3], bh[nt][0], bh[nt][1]);
                }
            }
        }
        __syncthreads();
    }

    // ---- epilogue 1: store C tile ----
#pragma unroll
    for (int mt = 0; mt < 4; mt++) {
        int r0 = row0 + wm * 64 + mt * 16 + g;
        int r1 = r0 + 8;
#pragma unroll
        for (int nt = 0; nt < 4; nt++) {
            int col = col0 + wn * 32 + nt * 8 + 2 * t;
            if (r0 < M)
                *(float2*)(C + (size_t)r0 * NF + col) = make_float2(acc[mt][nt][0], acc[mt][nt][1]);
            if (r1 < M)
                *(float2*)(C + (size_t)r1 * NF + col) = make_float2(acc[mt][nt][2], acc[mt][nt][3]);
        }
    }

    // ---- epilogue 2: fused alpha projection ----
    {
        float asv[4][2], adv[4][2];
#pragma unroll
        for (int nt = 0; nt < 4; nt++)
#pragma unroll
            for (int i = 0; i < 2; i++) {
                int gcol = col0 + wn * 32 + nt * 8 + 2 * t + i;
                asv[nt][i] = a_s[gcol];
                adv[nt][i] = a_d[gcol];
            }
        const int hd = (H == 4) ? ((col0 + wn * 32) >> 6) : 0;
#pragma unroll
        for (int mt = 0; mt < 4; mt++) {
            float sa0 = 0.f, sd0 = 0.f, sa1 = 0.f, sd1 = 0.f;
#pragma unroll
            for (int nt = 0; nt < 4; nt++)
#pragma unroll
                for (int i = 0; i < 2; i++) {
                    sa0 += acc[mt][nt][i]     * asv[nt][i];
                    sd0 += acc[mt][nt][i]     * adv[nt][i];
                    sa1 += acc[mt][nt][2 + i] * asv[nt][i];
                    sd1 += acc[mt][nt][2 + i] * adv[nt][i];
                }
#pragma unroll
            for (int o = 1; o <= 2; o <<= 1) {
                sa0 += __shfl_xor_sync(0xffffffffu, sa0, o);
                sd0 += __shfl_xor_sync(0xffffffffu, sd0, o);
                sa1 += __shfl_xor_sync(0xffffffffu, sa1, o);
                sd1 += __shfl_xor_sync(0xffffffffu, sd1, o);
            }
            if (t == 0) {
                int r0 = row0 + wm * 64 + mt * 16 + g;
                int r1 = r0 + 8;
                if (r0 < M) {
                    atomicAdd(&asrc[r0 * H + hd], sa0);
                    atomicAdd(&adst[r0 * H + hd], sd0);
                }
                if (r1 < M) {
                    atomicAdd(&asrc[r1 * H + hd], sa1);
                    atomicAdd(&adst[r1 * H + hd], sd1);
                }
            }
        }
    }
}

// ---------------- block-sum helper (64 threads, 2 warps) ---------------------
__device__ __forceinline__ float block_sum64(float v, float* red) {
#pragma unroll
    for (int o = 16; o > 0; o >>= 1) v += __shfl_xor_sync(0xffffffffu, v, o);
    int wid = threadIdx.x >> 5;
    if ((threadIdx.x & 31) == 0) red[wid] = v;
    __syncthreads();
    float s = red[0] + red[1];
    __syncthreads();
    return s;
}

// ---------------- fused aggregation + bias + LN + ELU -----------------------
template <int H>
__global__ void __launch_bounds__(64) agg_kernel(
    const float4* __restrict__ hfeat4,
    const float* __restrict__ asrc, const float* __restrict__ adst,
    const int* __restrict__ rowptr, const int* __restrict__ colsrc,
    const float* __restrict__ wexp,
    const float4* __restrict__ bias4, const float4* __restrict__ lnw4,
    const float4* __restrict__ lnb4, float4* __restrict__ out4)
{
    __shared__ float red[2];

    int i   = blockIdx.x;
    int tid = threadIdx.x;
    int head = (H == 4) ? (tid >> 4) : 0;

    float e0 = asrc[i * H + head] + adst[i * H + head];
    e0 = e0 > 0.f ? e0 : 0.2f * e0;
    float w0 = __expf(e0);
    float den = w0;
    float4 hv = hfeat4[(size_t)i * 64 + tid];
    float4 acc = make_float4(w0 * hv.x, w0 * hv.y, w0 * hv.z, w0 * hv.w);

    int beg = rowptr[i], end = rowptr[i + 1];
    int p = beg;
    for (; p + 4 <= end; p += 4) {
        int s0 = colsrc[p], s1 = colsrc[p + 1], s2 = colsrc[p + 2], s3 = colsrc[p + 3];
        float w_0 = wexp[(p + 0) * H + head];
        float w_1 = wexp[(p + 1) * H + head];
        float w_2 = wexp[(p + 2) * H + head];
        float w_3 = wexp[(p + 3) * H + head];
        float4 h0 = hfeat4[(size_t)s0 * 64 + tid];
        float4 h1 = hfeat4[(size_t)s1 * 64 + tid];
        float4 h2 = hfeat4[(size_t)s2 * 64 + tid];
        float4 h3 = hfeat4[(size_t)s3 * 64 + tid];
        den += (w_0 + w_1) + (w_2 + w_3);
        acc.x += w_0 * h0.x + w_1 * h1.x + w_2 * h2.x + w_3 * h3.x;
        acc.y += w_0 * h0.y + w_1 * h1.y + w_2 * h2.y + w_3 * h3.y;
        acc.z += w_0 * h0.z + w_1 * h1.z + w_2 * h2.z + w_3 * h3.z;
        acc.w += w_0 * h0.w + w_1 * h1.w + w_2 * h2.w + w_3 * h3.w;
    }
    for (; p < end; p++) {
        int s0 = colsrc[p];
        float wv = wexp[p * H + head];
        float4 h0 = hfeat4[(size_t)s0 * 64 + tid];
        den += wv;
        acc.x += wv * h0.x; acc.y += wv * h0.y; acc.z += wv * h0.z; acc.w += wv * h0.w;
    }

    float4 bv = bias4[tid];
    float inv = 1.f / den;
    float4 v = make_float4(acc.x * inv + bv.x, acc.y * inv + bv.y,
                           acc.z * inv + bv.z, acc.w * inv + bv.w);

    float mean = block_sum64(v.x + v.y + v.z + v.w, red) * (1.f / NF);
    float4 dl = make_float4(v.x - mean, v.y - mean, v.z - mean, v.w - mean);
    float var = block_sum64(dl.x * dl.x + dl.y * dl.y + dl.z * dl.z + dl.w * dl.w, red)
                * (1.f / NF);
    float rs = rsqrtf(var + 1e-5f);
    float4 wv4 = lnw4[tid];
    float4 bb = lnb4[tid];
    float4 y;
    y.x = dl.x * rs * wv4.x + bb.x;
    y.y = dl.y * rs * wv4.y + bb.y;
    y.z = dl.z * rs * wv4.z + bb.z;
    y.w = dl.w * rs * wv4.w + bb.w;
    y.x = y.x > 0.f ? y.x : expm1f(y.x);
    y.y = y.y > 0.f ? y.y : expm1f(y.y);
    y.z = y.z > 0.f ? y.z : expm1f(y.z);
    y.w = y.w > 0.f ? y.w : expm1f(y.w);
    out4[(size_t)i * 64 + tid] = y;
}

// ---------------- launch ----------------------------------------------------
extern "C" void kernel_launch(void* const* d_in, const int* in_sizes, int n_in,
                              void* d_out, int out_size) {
    const float* x    = (const float*)d_in[0];
    const int*   ei   = (const int*)d_in[1];
    const float* W0   = (const float*)d_in[2];
    const float* as0  = (const float*)d_in[3];
    const float* ad0  = (const float*)d_in[4];
    const float* b0   = (const float*)d_in[5];
    const float* lnw0 = (const float*)d_in[6];
    const float* lnb0 = (const float*)d_in[7];
    const float* W1   = (const float*)d_in[8];
    const float* as1  = (const float*)d_in[9];
    const float* ad1  = (const float*)d_in[10];
    const float* b1   = (const float*)d_in[11];
    const float* lnw1 = (const float*)d_in[12];
    const float* lnb1 = (const float*)d_in[13];
    const float* W2   = (const float*)d_in[14];
    const float* as2  = (const float*)d_in[15];
    const float* ad2  = (const float*)d_in[16];
    const float* b2   = (const float*)d_in[17];
    const float* lnw2 = (const float*)d_in[18];
    const float* lnb2 = (const float*)d_in[19];
    float* out = (float*)d_out;

    int n = in_sizes[0] / 512;   // 50000
    int e = in_sizes[1] / 2;     // 800000
    const int* src = ei;
    const int* dst = ei + e;

    float *ph, *pbuf, *palpha, *pwexp;
    int *pcnt, *prow, *pcur, *pcol, *pcds;
    uint32_t *pw0h, *pw0l, *pw1h, *pw1l, *pw2h, *pw2l;
    cudaGetSymbolAddress((void**)&ph, g_h);
    cudaGetSymbolAddress((void**)&pbuf, g_buf);
    cudaGetSymbolAddress((void**)&palpha, g_alpha);
    cudaGetSymbolAddress((void**)&pwexp, g_wexp);
    cudaGetSymbolAddress((void**)&pcnt, g_cnt);
    cudaGetSymbolAddress((void**)&prow, g_rowptr);
    cudaGetSymbolAddress((void**)&pcur, g_cursor);
    cudaGetSymbolAddress((void**)&pcol, g_colsrc);
    cudaGetSymbolAddress((void**)&pcds, g_coldst);
    cudaGetSymbolAddress((void**)&pw0h, g_w0h);
    cudaGetSymbolAddress((void**)&pw0l, g_w0l);
    cudaGetSymbolAddress((void**)&pw1h, g_w1h);
    cudaGetSymbolAddress((void**)&pw1l, g_w1l);
    cudaGetSymbolAddress((void**)&pw2h, g_w2h);
    cudaGetSymbolAddress((void**)&pw2l, g_w2l);

    float* pas0 = palpha + (size_t)0 * MAXN * 4;
    float* pad0 = palpha + (size_t)1 * MAXN * 4;
    float* pas1 = palpha + (size_t)2 * MAXN * 4;
    float* pad1 = palpha + (size_t)3 * MAXN * 4;
    float* pas2 = palpha + (size_t)4 * MAXN * 4;
    float* pad2 = palpha + (size_t)5 * MAXN * 4;

    const int TPB = 256;
    const int egrid = (e + TPB - 1) / TPB;
    // weight prep (1 MB total, ~5us) + CSR build
    prep_w_kernel<<<(256 * 256 + 2 * 256 * 128 + TPB - 1) / TPB, TPB>>>(
        W0, W1, W2, pw0h, pw0l, pw1h, pw1l, pw2h, pw2l);
    hist_kernel<<<egrid, TPB>>>(dst, pcnt, palpha, e);
    scan_kernel<<<1, 1024>>>(pcnt, prow, pcur, n);
    scatter_kernel<<<egrid, TPB>>>(src, dst, pcur, pcol, pcds, e);

    dim3 ggrid(NF / 128, (n + 127) / 128);

    // layer 0: GATConv(512 -> 4x64)
    gemm_bf16<4><<<ggrid, 256>>>(x, pw0h, pw0l, ph, n, 512, as0, ad0, pas0, pad0);
    weight_kernel<4><<<egrid, TPB>>>(pas0, pad0, pcol, pcds, pwexp, e);
    agg_kernel<4><<<n, 64>>>((const float4*)ph, pas0, pad0, prow, pcol, pwexp,
                             (const float4*)b0, (const float4*)lnw0,
                             (const float4*)lnb0, (float4*)pbuf);

    // layer 1: GATConv(256 -> 4x64)
    gemm_bf16<4><<<ggrid, 256>>>(pbuf, pw1h, pw1l, ph, n, 256, as1, ad1, pas1, pad1);
    weight_kernel<4><<<egrid, TPB>>>(pas1, pad1, pcol, pcds, pwexp, e);
    agg_kernel<4><<<n, 64>>>((const float4*)ph, pas1, pad1, prow, pcol, pwexp,
                             (const float4*)b1, (const float4*)lnw1,
                             (const float4*)lnb1, (float4*)pbuf);

    // layer 2: GATConv(256 -> 1x256)
    gemm_bf16<1><<<ggrid, 256>>>(pbuf, pw2h, pw2l, ph, n, 256, as2, ad2, pas2, pad2);
    weight_kernel<1><<<egrid, TPB>>>(pas2, pad2, pcol, pcds, pwexp, e);
    agg_kernel<1><<<n, 64>>>((const float4*)ph, pas2, pad2, prow, pcol, pwexp,
                             (const float4*)b2, (const float4*)lnw2,
                             (const float4*)lnb2, (float4*)out);
}